// round 1
// baseline (speedup 1.0000x reference)
#include <cuda_runtime.h>
#include <cstdint>

// Problem constants
#define BB   64
#define NN   100
#define DD   2048
#define NRH  16
#define DKH  64
#define DVH  128
#define PP   (BB*NN)        // 6400

// Scratch (no allocations allowed -> __device__ globals)
__device__ float g_K [PP * 1024];              // 26.2 MB
__device__ float g_Q [PP * 1024];              // 26.2 MB
__device__ float g_LG[BB * NRH * NN * NN];     // 41 MB: loggw[b][h][i][j]

// ---------------------------------------------------------------------------
// tf32 helpers (mma.sync m16n8k8, sm_80+ path; runs via HMMA on sm_103a)
// ---------------------------------------------------------------------------
__device__ __forceinline__ unsigned f2tf32(float f) {
    unsigned u;
    asm("cvt.rna.tf32.f32 %0, %1;" : "=r"(u) : "f"(f));
    return u;
}

__device__ __forceinline__ void mma_tf32(float& c0, float& c1, float& c2, float& c3,
                                         unsigned a0, unsigned a1, unsigned a2, unsigned a3,
                                         unsigned b0, unsigned b1)
{
    asm volatile(
        "mma.sync.aligned.m16n8k8.row.col.f32.tf32.tf32.f32 "
        "{%0,%1,%2,%3}, {%4,%5,%6,%7}, {%8,%9}, {%0,%1,%2,%3};"
        : "+f"(c0), "+f"(c1), "+f"(c2), "+f"(c3)
        : "r"(a0), "r"(a1), "r"(a2), "r"(a3), "r"(b0), "r"(b1));
}

// ---------------------------------------------------------------------------
// Kernel 1: projections  K = A@Wk + bk, Q = A@Wq + bq   (z selects K/Q)
// A: [6400, 2048] row-major, W: [2048, 1024] row-major (K-major = "col" B)
// Block 256 thr, tile BM=128 BN=128 BK=32, warp tile 64x32 (4 m-frag x 4 n-frag)
// ---------------------------------------------------------------------------
__global__ __launch_bounds__(256, 2)
void proj_kernel(const float* __restrict__ A,
                 const float* __restrict__ Wk, const float* __restrict__ bk,
                 const float* __restrict__ Wq, const float* __restrict__ bq)
{
    // sA transposed [k][m] stride 137 (conflict-free STS, ~2-way LDS worst case)
    // sB [k][n] stride 136 (conflict-free both directions)
    __shared__ __align__(16) unsigned sA[32 * 137];
    __shared__ __align__(16) unsigned sB[32 * 136];

    const float* W    = blockIdx.z ? Wq  : Wk;
    const float* bias = blockIdx.z ? bq  : bk;
    float*       outp = blockIdx.z ? g_Q : g_K;

    const int tid  = threadIdx.x;
    const int wid  = tid >> 5, lane = tid & 31;
    const int wm   = wid & 1,  wn   = wid >> 1;     // 2x4 warp grid
    const int g    = lane >> 2, t4  = lane & 3;
    const int mbase = blockIdx.y * 128;
    const int nbase = blockIdx.x * 128;

    float c[4][4][4];
    #pragma unroll
    for (int i = 0; i < 4; i++)
        #pragma unroll
        for (int j = 0; j < 4; j++)
            #pragma unroll
            for (int k = 0; k < 4; k++) c[i][j][k] = 0.f;

    for (int kt = 0; kt < 2048; kt += 32) {
        // A tile: 128 rows x 32 cols -> smem transposed, tf32-converted at store
        #pragma unroll
        for (int l = 0; l < 4; l++) {
            int id = tid + 256 * l;
            int r  = id >> 3;
            int cc = (id & 7) << 2;
            float4 v = *(const float4*)(A + (mbase + r) * 2048 + kt + cc);
            sA[(cc + 0) * 137 + r] = f2tf32(v.x);
            sA[(cc + 1) * 137 + r] = f2tf32(v.y);
            sA[(cc + 2) * 137 + r] = f2tf32(v.z);
            sA[(cc + 3) * 137 + r] = f2tf32(v.w);
        }
        // B tile: 32 rows x 128 cols
        #pragma unroll
        for (int l = 0; l < 4; l++) {
            int id = tid + 256 * l;
            int k  = id >> 5;
            int cc = (id & 31) << 2;
            float4 v = *(const float4*)(W + (kt + k) * 1024 + nbase + cc);
            uint4 u = make_uint4(f2tf32(v.x), f2tf32(v.y), f2tf32(v.z), f2tf32(v.w));
            *(uint4*)&sB[k * 136 + cc] = u;
        }
        __syncthreads();

        #pragma unroll
        for (int ks = 0; ks < 4; ks++) {
            const int k0 = ks * 8;
            unsigned af[4][4], bf[4][2];
            #pragma unroll
            for (int fm = 0; fm < 4; fm++) {
                int m0 = wm * 64 + fm * 16;
                af[fm][0] = sA[(k0 + t4    ) * 137 + m0 + g    ];
                af[fm][1] = sA[(k0 + t4    ) * 137 + m0 + g + 8];
                af[fm][2] = sA[(k0 + t4 + 4) * 137 + m0 + g    ];
                af[fm][3] = sA[(k0 + t4 + 4) * 137 + m0 + g + 8];
            }
            #pragma unroll
            for (int fn = 0; fn < 4; fn++) {
                int n0 = wn * 32 + fn * 8;
                bf[fn][0] = sB[(k0 + t4    ) * 136 + n0 + g];
                bf[fn][1] = sB[(k0 + t4 + 4) * 136 + n0 + g];
            }
            #pragma unroll
            for (int fm = 0; fm < 4; fm++)
                #pragma unroll
                for (int fn = 0; fn < 4; fn++)
                    mma_tf32(c[fm][fn][0], c[fm][fn][1], c[fm][fn][2], c[fm][fn][3],
                             af[fm][0], af[fm][1], af[fm][2], af[fm][3],
                             bf[fn][0], bf[fn][1]);
        }
        __syncthreads();
    }

    // epilogue: + bias, write fp32
    #pragma unroll
    for (int fm = 0; fm < 4; fm++) {
        int row = mbase + wm * 64 + fm * 16 + g;
        #pragma unroll
        for (int fn = 0; fn < 4; fn++) {
            int col = nbase + wn * 32 + fn * 8 + t4 * 2;
            float b0 = bias[col], b1 = bias[col + 1];
            float2 v01 = make_float2(c[fm][fn][0] + b0, c[fm][fn][1] + b1);
            float2 v23 = make_float2(c[fm][fn][2] + b0, c[fm][fn][3] + b1);
            *(float2*)(outp + row * 1024 + col)       = v01;
            *(float2*)(outp + (row + 8) * 1024 + col) = v23;
        }
    }
}

// ---------------------------------------------------------------------------
// Kernel 2: gate   loggw[b][h][i][j] = log(max(g_row . Wg[:,h] + bg[h], 1e-6))
// g_features [640000, 64]; 5000 blocks x 128 rows. Memory-bound (164 MB read).
// ---------------------------------------------------------------------------
__global__ __launch_bounds__(128)
void gate_kernel(const float* __restrict__ gf,
                 const float* __restrict__ Wg, const float* __restrict__ bg)
{
    __shared__ float sW[64 * 16];
    __shared__ float sb[16];
    __shared__ float sg[128 * 65];   // padded stride: bank = (tid + k) % 32

    const int tid = threadIdx.x;
    for (int i = tid; i < 1024; i += 128) sW[i] = Wg[i];
    if (tid < 16) sb[tid] = bg[tid];

    const int base = blockIdx.x * 128;
    for (int v = tid; v < 2048; v += 128) {       // 128 rows x 16 float4
        int r  = v >> 4;
        int cc = (v & 15) << 2;
        float4 x = *(const float4*)(gf + (base + r) * 64 + cc);
        sg[r * 65 + cc    ] = x.x;
        sg[r * 65 + cc + 1] = x.y;
        sg[r * 65 + cc + 2] = x.z;
        sg[r * 65 + cc + 3] = x.w;
    }
    __syncthreads();

    float acc[16];
    #pragma unroll
    for (int r = 0; r < 16; r++) acc[r] = sb[r];
    #pragma unroll 4
    for (int k = 0; k < 64; k++) {
        float gv = sg[tid * 65 + k];
        #pragma unroll
        for (int r = 0; r < 16; r++) acc[r] += gv * sW[k * 16 + r];
    }

    const int row = base + tid;
    const int b   = row / 10000;
    const int rem = row - b * 10000;              // = i*100 + j
    float* op = g_LG + b * 160000 + rem;
    #pragma unroll
    for (int r = 0; r < 16; r++)
        op[r * 10000] = logf(fmaxf(acc[r], 1e-6f));
}

// ---------------------------------------------------------------------------
// Kernel 3: attention per (b,h). 1024 blocks x 128 threads.
// S[i][j] = k_i.q_j/8 + loggw[i][j];  P = softmax over i;  out[j][d] = sum_i P V
// smem: sK/sQ (stride 65), sS (stride 101), sInv, sV (stride 132) = 145.7 KB
// ---------------------------------------------------------------------------
#define ATTN_SMEM_FLOATS (6500 + 6500 + 10100 + 128 + 13200)

__global__ __launch_bounds__(128)
void attn_kernel(const float* __restrict__ a,
                 const float* __restrict__ wsp, const float* __restrict__ bsp,
                 float* __restrict__ out)
{
    extern __shared__ float sm[];
    float* sK   = sm;               // 100*65
    float* sQ   = sK + 6500;        // 100*65
    float* sS   = sQ + 6500;        // 100*101
    float* sInv = sS + 10100;       // 128
    float* sV   = sInv + 128;       // 100*132

    const int h = blockIdx.x, b = blockIdx.y;
    const int tid = threadIdx.x;

    // load K, Q tiles [100 x 64]
    const float* Kg = g_K + (b * 100) * 1024 + h * 64;
    const float* Qg = g_Q + (b * 100) * 1024 + h * 64;
    for (int v = tid; v < 1600; v += 128) {
        int i  = v >> 4;
        int cc = (v & 15) << 2;
        float4 kv = *(const float4*)(Kg + i * 1024 + cc);
        float4 qv = *(const float4*)(Qg + i * 1024 + cc);
        sK[i*65+cc] = kv.x; sK[i*65+cc+1] = kv.y; sK[i*65+cc+2] = kv.z; sK[i*65+cc+3] = kv.w;
        sQ[i*65+cc] = qv.x; sQ[i*65+cc+1] = qv.y; sQ[i*65+cc+2] = qv.z; sQ[i*65+cc+3] = qv.w;
    }
    __syncthreads();

    // S: 25x25 grid of 4x4 register tiles (i varies fastest across lanes)
    const float* LG = g_LG + (b * 16 + h) * 10000;
    for (int tt = tid; tt < 625; tt += 128) {
        int i0 = (tt % 25) << 2;
        int j0 = (tt / 25) << 2;
        float acc[4][4] = {};
        #pragma unroll 4
        for (int d = 0; d < 64; d++) {
            float kv[4], qv[4];
            #pragma unroll
            for (int ii = 0; ii < 4; ii++) kv[ii] = sK[(i0 + ii) * 65 + d];
            #pragma unroll
            for (int jj = 0; jj < 4; jj++) qv[jj] = sQ[(j0 + jj) * 65 + d];
            #pragma unroll
            for (int ii = 0; ii < 4; ii++)
                #pragma unroll
                for (int jj = 0; jj < 4; jj++) acc[ii][jj] += kv[ii] * qv[jj];
        }
        #pragma unroll
        for (int ii = 0; ii < 4; ii++)
            #pragma unroll
            for (int jj = 0; jj < 4; jj++)
                sS[(i0 + ii) * 101 + j0 + jj] =
                    acc[ii][jj] * 0.125f + LG[(i0 + ii) * 100 + j0 + jj];
    }
    __syncthreads();

    // column softmax over i (thread j). Keep un-normalized exp; fold 1/sum later.
    if (tid < 100) {
        float m = -1e30f;
        for (int i = 0; i < 100; i++) m = fmaxf(m, sS[i * 101 + tid]);
        float s = 0.f;
        for (int i = 0; i < 100; i++) {
            float e = __expf(sS[i * 101 + tid] - m);
            sS[i * 101 + tid] = e;
            s += e;
        }
        sInv[tid] = 1.f / s;
    }

    // V load [100 x 128] (separate smem region; overlaps softmax tail threads)
    for (int v = tid; v < 3200; v += 128) {
        int i  = v >> 5;
        int cc = (v & 31) << 2;
        float4 vv = *(const float4*)(a + (b * 100 + i) * 2048 + h * 128 + cc);
        *(float4*)(sV + i * 132 + cc) = vv;
    }
    __syncthreads();

    // PV: out[j][d] = inv[j] * sum_i e[i][j] * V[i][d]; tiles 4j x 8d
    const float wsc = *wsp;
    const float bsc = *bsp;
    for (int tt = tid; tt < 400; tt += 128) {
        int d0 = (tt & 15) << 3;
        int j0 = (tt >> 4) << 2;
        float acc[4][8] = {};
        for (int i = 0; i < 100; i++) {
            float4 v0 = *(const float4*)(sV + i * 132 + d0);
            float4 v1 = *(const float4*)(sV + i * 132 + d0 + 4);
            float vv[8] = {v0.x, v0.y, v0.z, v0.w, v1.x, v1.y, v1.z, v1.w};
            float p[4];
            #pragma unroll
            for (int jj = 0; jj < 4; jj++) p[jj] = sS[i * 101 + j0 + jj];
            #pragma unroll
            for (int jj = 0; jj < 4; jj++)
                #pragma unroll
                for (int dd = 0; dd < 8; dd++) acc[jj][dd] += p[jj] * vv[dd];
        }
        #pragma unroll
        for (int jj = 0; jj < 4; jj++) {
            float sc = sInv[j0 + jj] * wsc;
            float* op = out + (b * 100 + j0 + jj) * 2048 + h * 128 + d0;
            #pragma unroll
            for (int dd = 0; dd < 8; dd++) op[dd] = acc[jj][dd] * sc + bsc;
        }
    }
}

// ---------------------------------------------------------------------------
// Launch. Inputs (metadata order): a_features, g_features, split,
// rel_pair_counts, W_g, b_g, W_K, b_K, W_Q, b_Q, w_s, b_s
// ---------------------------------------------------------------------------
extern "C" void kernel_launch(void* const* d_in, const int* in_sizes, int n_in,
                              void* d_out, int out_size)
{
    (void)in_sizes; (void)n_in; (void)out_size;
    const float* a  = (const float*)d_in[0];
    const float* gf = (const float*)d_in[1];
    const float* Wg = (const float*)d_in[4];
    const float* bg = (const float*)d_in[5];
    const float* Wk = (const float*)d_in[6];
    const float* bk = (const float*)d_in[7];
    const float* Wq = (const float*)d_in[8];
    const float* bq = (const float*)d_in[9];
    const float* ws = (const float*)d_in[10];
    const float* bs = (const float*)d_in[11];
    float* out = (float*)d_out;

    cudaFuncSetAttribute(attn_kernel,
                         cudaFuncAttributeMaxDynamicSharedMemorySize,
                         ATTN_SMEM_FLOATS * (int)sizeof(float));

    proj_kernel<<<dim3(8, 50, 2), 256>>>(a, Wk, bk, Wq, bq);
    gate_kernel<<<5000, 128>>>(gf, Wg, bg);
    attn_kernel<<<dim3(16, 64), 128, ATTN_SMEM_FLOATS * sizeof(float)>>>(a, ws, bs, out);
}